// round 1
// baseline (speedup 1.0000x reference)
#include <cuda_runtime.h>
#include <cstdint>

#define K_DIM      128
#define O_DIM      128
#define CHUNK      64          // rows of x per pipeline stage
#define THREADS    256         // 8 warps: 4 o-groups x 2 m-groups
#define LDS_STRIDE 132         // 128 + 4 padding -> conflict-free frag loads
#define SMEM_FLOATS (O_DIM*LDS_STRIDE + 2*CHUNK*LDS_STRIDE)
#define SMEM_BYTES  (SMEM_FLOATS * 4)

__device__ __forceinline__ uint32_t cvt_tf32(float f) {
    uint32_t r;
    asm("cvt.rna.tf32.f32 %0, %1;" : "=r"(r) : "f"(f));
    return r;
}

__device__ __forceinline__ void cp_async16(uint32_t smem_addr, const void* gptr) {
    asm volatile("cp.async.cg.shared.global [%0], [%1], 16;" :: "r"(smem_addr), "l"(gptr));
}
__device__ __forceinline__ void cp_commit() {
    asm volatile("cp.async.commit_group;");
}

__global__ void __launch_bounds__(THREADS, 1)
qlinear_tf32_kernel(const float* __restrict__ x,
                    const float* __restrict__ W,
                    float* __restrict__ out,
                    int nrows, int nchunks)
{
    extern __shared__ float smem[];
    float* ws  = smem;                              // [128][132]  W row-major (o,k)
    float* xs0 = smem + O_DIM * LDS_STRIDE;         // [64][132]
    float* xs1 = xs0 + CHUNK * LDS_STRIDE;

    const int tid = threadIdx.x;
    const uint32_t ws_a  = (uint32_t)__cvta_generic_to_shared(ws);
    const uint32_t xs_a0 = (uint32_t)__cvta_generic_to_shared(xs0);
    const uint32_t xs_a1 = (uint32_t)__cvta_generic_to_shared(xs1);

    // ---- stage W (coalesced float4, row-major, padded) ----
    #pragma unroll
    for (int j = 0; j < 16; j++) {
        int flat = tid + j * THREADS;               // 0..4095 float4s
        int o  = flat >> 5;                         // 0..127
        int c4 = flat & 31;                         // 0..31
        cp_async16(ws_a + (uint32_t)(o * LDS_STRIDE + c4 * 4) * 4,
                   W + o * K_DIM + c4 * 4);
    }

    // ---- chunk staging helper ----
    auto stage = [&](int chunk, int buf) {
        int row0 = chunk * CHUNK;
        uint32_t base = buf ? xs_a1 : xs_a0;
        #pragma unroll
        for (int j = 0; j < 8; j++) {
            int flat = tid + j * THREADS;           // 0..2047 float4s
            int r  = flat >> 5;                     // 0..63
            int c4 = flat & 31;
            int gr = row0 + r;
            if (gr >= nrows) gr = nrows - 1;        // clamp: never OOB, data unused
            cp_async16(base + (uint32_t)(r * LDS_STRIDE + c4 * 4) * 4,
                       x + (size_t)gr * K_DIM + c4 * 4);
        }
    };

    const int c0 = blockIdx.x;
    if (c0 < nchunks) stage(c0, 0);
    cp_commit();                                    // group: W + chunk0
    const int c1 = c0 + gridDim.x;
    const bool have1 = (c1 < nchunks);
    if (have1) { stage(c1, 1); cp_commit(); }
    if (have1) asm volatile("cp.async.wait_group 1;");
    else       asm volatile("cp.async.wait_group 0;");
    __syncthreads();                                // ws + xs0 visible to all

    // ---- per-warp geometry ----
    const int lane = tid & 31, wid = tid >> 5;
    const int q = lane >> 2;        // groupID (0..7)
    const int t = lane & 3;         // threadID in group (0..3)
    const int wo = wid & 3;         // o-group: cols [wo*32, wo*32+32)
    const int wm = wid >> 2;        // m-group: rows [wm*32, wm*32+32) of chunk

    // ---- B fragments: all of this warp's W slice, held in registers ----
    // B element (k, n) = W[n][k]; n = wo*32 + tt*8 + q; b0: k=8s+t, b1: k=8s+t+4
    uint32_t Bf[16][4][2];
    #pragma unroll
    for (int s = 0; s < 16; s++)
        #pragma unroll
        for (int tt = 0; tt < 4; tt++) {
            const float* p = ws + (wo * 32 + tt * 8 + q) * LDS_STRIDE + s * 8 + t;
            Bf[s][tt][0] = cvt_tf32(p[0]);
            Bf[s][tt][1] = cvt_tf32(p[4]);
        }

    // ---- main grid-stride pipeline over 64-row chunks ----
    int i = 0;
    for (int c = c0; c < nchunks; c += gridDim.x, i++) {
        const float* xb = (i & 1) ? xs1 : xs0;

        #pragma unroll
        for (int mt = 0; mt < 2; mt++) {
            const int mrow = wm * 32 + mt * 16;
            float acc[4][4];
            #pragma unroll
            for (int tt = 0; tt < 4; tt++)
                #pragma unroll
                for (int e = 0; e < 4; e++) acc[tt][e] = 0.0f;

            #pragma unroll
            for (int s = 0; s < 16; s++) {
                const float* a0p = xb + (mrow + q) * LDS_STRIDE + s * 8 + t;
                const float* a1p = a0p + 8 * LDS_STRIDE;
                uint32_t a0 = cvt_tf32(a0p[0]);
                uint32_t a2 = cvt_tf32(a0p[4]);
                uint32_t a1 = cvt_tf32(a1p[0]);
                uint32_t a3 = cvt_tf32(a1p[4]);
                #pragma unroll
                for (int tt = 0; tt < 4; tt++) {
                    asm volatile(
                        "mma.sync.aligned.m16n8k8.row.col.f32.tf32.tf32.f32 "
                        "{%0,%1,%2,%3}, {%4,%5,%6,%7}, {%8,%9}, {%0,%1,%2,%3};"
                        : "+f"(acc[tt][0]), "+f"(acc[tt][1]),
                          "+f"(acc[tt][2]), "+f"(acc[tt][3])
                        : "r"(a0), "r"(a1), "r"(a2), "r"(a3),
                          "r"(Bf[s][tt][0]), "r"(Bf[s][tt][1]));
                }
            }

            // epilogue: C frag -> gmem, 8B sector-aligned float2 stores
            const int r1 = c * CHUNK + mrow + q;
            const int r2 = r1 + 8;
            #pragma unroll
            for (int tt = 0; tt < 4; tt++) {
                const int col = wo * 32 + tt * 8 + 2 * t;
                if (r1 < nrows)
                    *reinterpret_cast<float2*>(out + (size_t)r1 * O_DIM + col) =
                        make_float2(acc[tt][0], acc[tt][1]);
                if (r2 < nrows)
                    *reinterpret_cast<float2*>(out + (size_t)r2 * O_DIM + col) =
                        make_float2(acc[tt][2], acc[tt][3]);
            }
        }

        __syncthreads();                            // all warps done with this buffer
        int cnext2 = c + 2 * gridDim.x;
        if (cnext2 < nchunks) {
            stage(cnext2, i & 1);                   // refill the buffer just consumed
            cp_commit();
            asm volatile("cp.async.wait_group 1;"); // next buffer (issued 2 ago) done
        } else {
            asm volatile("cp.async.wait_group 0;");
        }
        __syncthreads();
    }
}

extern "C" void kernel_launch(void* const* d_in, const int* in_sizes, int n_in,
                              void* d_out, int out_size)
{
    const float* x = (const float*)d_in[0];
    const float* W = (const float*)d_in[1];
    float* out = (float*)d_out;

    const int nrows   = in_sizes[0] / K_DIM;
    const int nchunks = (nrows + CHUNK - 1) / CHUNK;

    cudaFuncSetAttribute(qlinear_tf32_kernel,
                         cudaFuncAttributeMaxDynamicSharedMemorySize, SMEM_BYTES);

    int sms = 148;
    cudaDeviceGetAttribute(&sms, cudaDevAttrMultiProcessorCount, 0);
    int grid = sms;
    if (grid > nchunks) grid = nchunks;
    if (grid < 1) grid = 1;

    qlinear_tf32_kernel<<<grid, THREADS, SMEM_BYTES>>>(x, W, out, nrows, nchunks);
}